// round 14
// baseline (speedup 1.0000x reference)
#include <cuda_runtime.h>
#include <cstdint>

#define NGR  64
#define NN   2048
#define NH   1024            // nodes per half (per CTA)
#define EPG  16384           // edges per graph
#define KK   410
#define HH   3
#define CC   20
#define T    1024
#define NW   (T / 32)        // 32 — scan_ex relies on NW == 32
#define EPT  (EPG / T)       // 16 edges cached per thread

// ---------------- dynamic smem layout (bytes, per CTA) ----------------------
#define SZ_A     104960
#define O_CSR    SZ_A                   // int[10240] own-half CSR
#define O_CNT    (O_CSR + 40960)        // int[1024]
#define O_OFF    (O_CNT + 4096)         // int[1024]
#define O_CUR    (O_OFF + 4096)         // int[1024]
#define O_DINV   (O_CUR + 4096)         // float[2048]
#define O_HSS    (O_DINV + 8192)        // hss; radix bins; als+perm later
#define O_SCR    (O_HSS + 8192)         // score own half; ald later
#define O_ENC    (O_SCR + 8192)         // u32[2048]
#define O_NEW    (O_ENC + 8192)         // member list (select); newidx; temps
#define SMEM_TOTAL (O_NEW + 8192)       // 199168

#define O_ALS    O_HSS                  // float[1230]
#define O_PERM   (O_HSS + 4920)         // int[410]
#define O_ALD    O_SCR                  // float[1230]
#define O_PART   O_NEW                  // float[16*60]
#define O_GSUM   (O_NEW + 3840)         // float[60]
#define O_HB     (O_NEW + 4352)         // float[30]
#define O_ZB     (O_NEW + 4480)         // float[3]

__device__ __forceinline__ float lrelu(float x) { return x > 0.f ? x : 0.2f * x; }
__device__ __forceinline__ unsigned encf(float f) {
    unsigned u = __float_as_uint(f);
    return (u & 0x80000000u) ? ~u : (u | 0x80000000u);
}
__device__ __forceinline__ uint32_t s2u(const void* p) {
    return (uint32_t)__cvta_generic_to_shared(p);
}
__device__ __forceinline__ uint32_t mapa_u32(uint32_t a, uint32_t r) {
    uint32_t d; asm("mapa.shared::cluster.u32 %0, %1, %2;" : "=r"(d) : "r"(a), "r"(r));
    return d;
}
__device__ __forceinline__ float ldc_f32(uint32_t a) {
    float v; asm volatile("ld.shared::cluster.f32 %0, [%1];" : "=f"(v) : "r"(a)); return v;
}
__device__ __forceinline__ unsigned ldc_u32(uint32_t a) {
    unsigned v; asm volatile("ld.shared::cluster.u32 %0, [%1];" : "=r"(v) : "r"(a)); return v;
}
__device__ __forceinline__ float4 ldc_f4(uint32_t a) {
    float4 v;
    asm volatile("ld.shared::cluster.v4.f32 {%0,%1,%2,%3}, [%4];"
                 : "=f"(v.x), "=f"(v.y), "=f"(v.z), "=f"(v.w) : "r"(a));
    return v;
}
#define CLUSTER_SYNC() do { \
    asm volatile("barrier.cluster.arrive.aligned;" ::: "memory"); \
    asm volatile("barrier.cluster.wait.aligned;" ::: "memory"); } while (0)

// block-wide exclusive scan of per-thread sums; 2 barriers, no serial loop.
// Requires NW == 32.
__device__ __forceinline__ int scan_ex(int s, int t, int* wsum) {
    __syncthreads();
    int lane = t & 31, wid = t >> 5;
    int x = s;
#pragma unroll
    for (int d = 1; d < 32; d <<= 1) {
        int y = __shfl_up_sync(0xFFFFFFFFu, x, d);
        if (lane >= d) x += y;
    }
    if (lane == 31) wsum[wid] = x;
    __syncthreads();
    int w = wsum[lane];
    int incl = w;
#pragma unroll
    for (int d = 1; d < 32; d <<= 1) {
        int y = __shfl_up_sync(0xFFFFFFFFu, incl, d);
        if (lane >= d) incl += y;
    }
    int wpre = __shfl_sync(0xFFFFFFFFu, incl - w, wid);
    return wpre + x - s;
}

__global__ void __launch_bounds__(T, 1) __cluster_dims__(2, 1, 1)
k_mega(const float* __restrict__ x,
       const int* __restrict__ src, const int* __restrict__ dst,
       const float* __restrict__ W1, const float* __restrict__ b1,
       const float* __restrict__ Ws, const float* __restrict__ bs,
       const float* __restrict__ Wg,
       const float* __restrict__ a_src, const float* __restrict__ a_dst,
       const float* __restrict__ bg,
       const float* __restrict__ Wf1, const float* __restrict__ bf1,
       const float* __restrict__ Wf2, const float* __restrict__ bf2,
       float* __restrict__ out)
{
    extern __shared__ char sm[];
    float*    s_hx   = (float*)(sm);                 // rows of 12 (full graph)
    float*    s_hG   = (float*)(sm);                 // rows of 64 by global j
    int*      s_csr  = (int*)(sm + O_CSR);
    int*      s_cnt  = (int*)(sm + O_CNT);
    int*      s_off  = (int*)(sm + O_OFF);
    int*      s_cur  = (int*)(sm + O_CUR);
    float*    s_dinv = (float*)(sm + O_DINV);
    float*    s_hss  = (float*)(sm + O_HSS);
    int*      s_bins = (int*)(sm + O_HSS);
    float*    s_als  = (float*)(sm + O_ALS);
    int*      s_perm = (int*)(sm + O_PERM);
    float*    s_scr  = (float*)(sm + O_SCR);
    float*    s_ald  = (float*)(sm + O_ALD);
    unsigned* s_enc  = (unsigned*)(sm + O_ENC);
    int*      s_new  = (int*)(sm + O_NEW);
    int*      s_mem  = (int*)(sm + O_NEW);           // select member list
    float*    s_part = (float*)(sm + O_PART);
    float*    s_gsum = (float*)(sm + O_GSUM);
    float*    s_hb   = (float*)(sm + O_HB);
    float*    s_zb   = (float*)(sm + O_ZB);

    __shared__ float W1s[50], Wss[10], b1s[10], Wgs[600], asr[60], ads[60];
    __shared__ int wsum[NW];
    __shared__ unsigned sPrefix;
    __shared__ int sNeed, sM;
    __shared__ unsigned long long sKT;

    const int g    = blockIdx.x >> 1;
    const unsigned rank = blockIdx.x & 1;
    const unsigned peer = rank ^ 1;
    const int t = threadIdx.x;
    const int ebase = g * EPG;
    const int nbase = g * NN;
    const int hbase = (int)rank * NH;
    const float bs0 = bs[0];

    // ---- P0: register-cache full edge list + init + weights ----
    unsigned er[EPT];
    {
        const int4* s4 = (const int4*)(src + ebase);
        const int4* d4 = (const int4*)(dst + ebase);
#pragma unroll
        for (int r = 0; r < EPT / 4; r++) {
            int4 dv = d4[t + r * T];
            int4 sv = s4[t + r * T];
            er[r * 4 + 0] = ((unsigned)(dv.x & (NN - 1)) << 11) | (unsigned)(sv.x & (NN - 1));
            er[r * 4 + 1] = ((unsigned)(dv.y & (NN - 1)) << 11) | (unsigned)(sv.y & (NN - 1));
            er[r * 4 + 2] = ((unsigned)(dv.z & (NN - 1)) << 11) | (unsigned)(sv.z & (NN - 1));
            er[r * 4 + 3] = ((unsigned)(dv.w & (NN - 1)) << 11) | (unsigned)(sv.w & (NN - 1));
        }
    }
    s_cnt[t] = 0;
    if (t < 50) W1s[t] = W1[t];
    if (t < 10) { Wss[t] = Ws[t]; b1s[t] = b1[t]; }
    if (t < 600) Wgs[t] = Wg[t];
    if (t < 60) { asr[t] = a_src[t]; ads[t] = a_dst[t]; }
    __syncthreads();

    // ---- P1: degree count (own-half dsts only) ----
#pragma unroll
    for (int r = 0; r < EPT; r++)
        if ((er[r] >> 21) == rank) atomicAdd(&s_cnt[(er[r] >> 11) & (NH - 1)], 1);

    // ---- P2a: scan + own dinv ----
    {
        __syncthreads();
        int v = s_cnt[t];
        int ex = scan_ex(v, t, wsum);
        s_off[t] = ex; s_cur[t] = ex;
        s_dinv[hbase + t] = rsqrtf((float)v + 1.0f);
    }
    __syncthreads();

    // ---- P3: own-half CSR scatter ----
#pragma unroll
    for (int r = 0; r < EPT; r++) {
        if ((er[r] >> 21) == rank) {
            int dl = (int)((er[r] >> 11) & (NH - 1));
            s_csr[atomicAdd(&s_cur[dl], 1)] = (int)(er[r] & (NN - 1));
        }
    }

    // ---- prefetch x into regs (er dead); LDG flies during cluster wait ----
    float xi0[5], xi1[5];
    {
        const float* xb = x + (size_t)nbase * 5;
#pragma unroll
        for (int c = 0; c < 5; c++) xi0[c] = xb[t * 5 + c];
#pragma unroll
        for (int c = 0; c < 5; c++) xi1[c] = xb[(t + T) * 5 + c];
    }
    CLUSTER_SYNC();     // own dinv half + CSR done in both CTAs

    // ---- P2b: copy peer dinv half; P4: hh1 for ALL nodes (replicated) ----
    {
        int i = (int)peer * NH + t;
        s_dinv[i] = ldc_f32(mapa_u32(s2u(&s_dinv[i]), peer));
    }
    __syncthreads();
#pragma unroll
    for (int q = 0; q < 2; q++) {
        int i = t + q * T;
        float dv = s_dinv[i];
        const float* xi = q ? xi1 : xi0;
        float h[12];
#pragma unroll
        for (int k = 0; k < 10; k++) {
            float vv = 0.f;
#pragma unroll
            for (int c = 0; c < 5; c++) vv += xi[c] * W1s[c * 10 + k];
            h[k] = vv * dv;
        }
        h[10] = 0.f; h[11] = 0.f;
        float4* o = (float4*)&s_hx[i * 12];
        o[0] = make_float4(h[0], h[1], h[2], h[3]);
        o[1] = make_float4(h[4], h[5], h[6], h[7]);
        o[2] = make_float4(h[8], h[9], h[10], h[11]);
    }
    __syncthreads();

    // ---- P5: GCN1 gather for own 1024 dsts + scorer hss ----
    {
        int i = hbase + t;
        const float4* me = (const float4*)&s_hx[i * 12];
        float4 a0 = me[0], a1 = me[1], a2 = me[2];
        int e0 = s_off[t], e1 = e0 + s_cnt[t];
        for (int e = e0; e < e1; e++) {
            const float4* r = (const float4*)&s_hx[s_csr[e] * 12];
            float4 r0 = r[0], r1 = r[1], r2 = r[2];
            a0.x += r0.x; a0.y += r0.y; a0.z += r0.z; a0.w += r0.w;
            a1.x += r1.x; a1.y += r1.y; a1.z += r1.z; a1.w += r1.w;
            a2.x += r2.x; a2.y += r2.y;
        }
        __syncthreads();     // all local hh1 reads done before x1 overwrite
        float dv = s_dinv[i];
        float v[10] = {a0.x, a0.y, a0.z, a0.w, a1.x, a1.y, a1.z, a1.w, a2.x, a2.y};
        float hs = 0.f;
#pragma unroll
        for (int k = 0; k < 10; k++) {
            v[k] = v[k] * dv + b1s[k];
            hs += v[k] * Wss[k];
        }
        float4* o = (float4*)&s_hx[i * 12];
        o[0] = make_float4(v[0], v[1], v[2], v[3]);
        o[1] = make_float4(v[4], v[5], v[6], v[7]);
        o[2] = make_float4(v[8], v[9], 0.f, 0.f);
        s_hss[i] = hs * dv;
    }
    CLUSTER_SYNC();     // peer hss half ready

    // ---- P5b: copy peer hss half ----
    {
        int i = (int)peer * NH + t;
        s_hss[i] = ldc_f32(mapa_u32(s2u(&s_hss[i]), peer));
    }
    __syncthreads();

    // ---- P6: scorer gather for own dsts -> score + enc ----
    {
        int i = hbase + t;
        float sc = s_hss[i];
        int e0 = s_off[t], e1 = e0 + s_cnt[t];
        for (int e = e0; e < e1; e++) sc += s_hss[s_csr[e]];
        sc = sc * s_dinv[i] + bs0;
        s_scr[i] = sc;
        s_enc[i] = encf(sc);
    }
    CLUSTER_SYNC();     // peer enc half ready

    // ---- P6b: copy peer enc half ----
    {
        int i = (int)peer * NH + t;
        s_enc[i] = ldc_u32(mapa_u32(s2u(&s_enc[i]), peer));
    }
    __syncthreads();
    unsigned e0v = s_enc[2 * t];
    unsigned e1v = s_enc[2 * t + 1];

    // ---- P7: top-K — 2 radix passes (11+11 bits) + exact member stage.
    //      Redundant in both CTAs; value-based -> identical results. ----
    {
        int i0 = 2 * t;
        if (t == 0) sM = 0;

        // pass 0: bits [21,32)
        s_bins[i0] = 0; s_bins[i0 + 1] = 0;
        __syncthreads();
        atomicAdd(&s_bins[e0v >> 21], 1);
        atomicAdd(&s_bins[e1v >> 21], 1);
        __syncthreads();
        int c0 = s_bins[2047 - i0], c1 = s_bins[2046 - i0];
        int ex = scan_ex(c0 + c1, t, wsum);
        if (ex < KK && KK <= ex + c0)                 { sPrefix = (unsigned)(2047 - i0); sNeed = KK - ex; }
        else if (ex + c0 < KK && KK <= ex + c0 + c1)  { sPrefix = (unsigned)(2046 - i0); sNeed = KK - ex - c0; }
        __syncthreads();
        unsigned pfx0 = sPrefix;
        int need0 = sNeed;

        // pass 1: bits [10,21)
        s_bins[i0] = 0; s_bins[i0 + 1] = 0;
        __syncthreads();
        if ((e0v >> 21) == pfx0) atomicAdd(&s_bins[(e0v >> 10) & 2047], 1);
        if ((e1v >> 21) == pfx0) atomicAdd(&s_bins[(e1v >> 10) & 2047], 1);
        __syncthreads();
        c0 = s_bins[2047 - i0]; c1 = s_bins[2046 - i0];
        ex = scan_ex(c0 + c1, t, wsum);
        if (ex < need0 && need0 <= ex + c0)                 { sPrefix = (pfx0 << 11) | (unsigned)(2047 - i0); sNeed = need0 - ex; }
        else if (ex + c0 < need0 && need0 <= ex + c0 + c1)  { sPrefix = (pfx0 << 11) | (unsigned)(2046 - i0); sNeed = need0 - ex - c0; }
        __syncthreads();
        unsigned pfx22 = sPrefix;
        int need1 = sNeed;

        // exact stage: members of the 22-bit threshold bin (expected tiny).
        // Unique key (enc<<11)|(2047-idx) -> deterministic across CTAs.
        if ((e0v >> 10) == pfx22) s_mem[atomicAdd(&sM, 1)] = i0;
        if ((e1v >> 10) == pfx22) s_mem[atomicAdd(&sM, 1)] = i0 + 1;
        __syncthreads();
        int M = sM;
        for (int m = t; m < M; m += T) {
            int im = s_mem[m];
            unsigned long long km =
                ((unsigned long long)s_enc[im] << 11) | (unsigned)(2047 - im);
            int r = 0;
            for (int q = 0; q < M; q++) {
                int iq = s_mem[q];
                unsigned long long kq =
                    ((unsigned long long)s_enc[iq] << 11) | (unsigned)(2047 - iq);
                r += (kq > km) ? 1 : 0;
            }
            if (r == need1 - 1) sKT = km;   // unique writer
        }
        __syncthreads();
        unsigned long long KT = sKT;        // KK-th largest unique key

        // single-scan compaction: key >= KT selects exactly KK nodes
        unsigned long long k0 = ((unsigned long long)e0v << 11) | (unsigned)(2047 - i0);
        unsigned long long k1 = ((unsigned long long)e1v << 11) | (unsigned)(2046 - i0);
        int p0 = (k0 >= KT) ? 1 : 0;
        int p1 = (k1 >= KT) ? 1 : 0;
        int exg = scan_ex(p0 + p1, t, wsum);   // leading barrier guards s_mem reads
        if (p0) { s_perm[exg] = i0; s_new[i0] = exg; } else s_new[i0] = -1;
        if (p1) { s_perm[exg + p0] = i0 + 1; s_new[i0 + 1] = exg + p0; }
        else s_new[i0 + 1] = -1;
    }
    __syncthreads();

    // ---- P8: pooled precompute for OWNED (node,head) units (gate inline) ----
    {
        float hg[2][CC], as2[2], ad2[2];
        bool act[2] = {false, false};
#pragma unroll
        for (int pass = 0; pass < 2; pass++) {
            int u = t + pass * T;
            if (u >= KK * HH) break;
            int j = u / 3, h = u - 3 * j;
            int node = s_perm[j];
            if ((node >> 10) != (int)rank) continue;
            act[pass] = true;
            float gate = tanhf(s_scr[node]);
            float xp[10];
#pragma unroll
            for (int c = 0; c < 10; c++) xp[c] = s_hx[node * 12 + c] * gate;
            float as = 0.f, ad = 0.f;
#pragma unroll
            for (int c = 0; c < CC; c++) {
                int k = h * CC + c;
                float v = 0.f;
#pragma unroll
                for (int q = 0; q < 10; q++) v += xp[q] * Wgs[q * 60 + k];
                hg[pass][c] = v;
                as += v * asr[k];
                ad += v * ads[k];
            }
            as2[pass] = as; ad2[pass] = ad;
        }
        __syncthreads();   // all local x1/scr reads done
#pragma unroll
        for (int pass = 0; pass < 2; pass++) {
            int u = t + pass * T;
            if (u >= KK * HH || !act[pass]) continue;
            int j = u / 3, h = u - 3 * j;
#pragma unroll
            for (int c = 0; c < CC; c++) s_hG[j * 64 + h * CC + c] = hg[pass][c];
            s_als[u] = as2[pass];
            s_ald[u] = ad2[pass];
        }
    }
    CLUSTER_SYNC();     // peer hG rows + als entries final

    // ---- P9: GAT softmax-aggregate for owned units; peer als/hG via DSMEM ----
    // logits ~1e-2: exp without max-subtraction is exact softmax.
    {
        float acc[2][CC];
        bool act[2] = {false, false};
#pragma unroll
        for (int pass = 0; pass < 2; pass++) {
            int u = t + pass * T;
            if (u >= KK * HH) break;
            int j = u / 3, h = u - 3 * j;
            int node = s_perm[j];
            if ((node >> 10) != (int)rank) continue;
            act[pass] = true;
            float aldj = s_ald[u];
            float w = __expf(lrelu(s_als[u] + aldj));
            float den = w;
#pragma unroll
            for (int c = 0; c < CC; c++) acc[pass][c] = s_hG[j * 64 + h * CC + c] * w;
            int nl = node & (NH - 1);
            int e0 = s_off[nl], e1 = e0 + s_cnt[nl];
            for (int e = e0; e < e1; e++) {
                int sj = s_new[s_csr[e]];
                if (sj < 0) continue;
                bool rem = ((s_perm[sj] >> 10) != (int)rank);
                float alsj = rem
                    ? ldc_f32(mapa_u32(s2u(&s_als[sj * 3 + h]), peer))
                    : s_als[sj * 3 + h];
                float ww = __expf(lrelu(alsj + aldj));
                den += ww;
                if (!rem) {
                    const float* row = &s_hG[sj * 64 + h * CC];
#pragma unroll
                    for (int c = 0; c < CC; c++) acc[pass][c] += row[c] * ww;
                } else {
                    uint32_t ra = mapa_u32(s2u(&s_hG[sj * 64 + h * CC]), peer);
#pragma unroll
                    for (int c4 = 0; c4 < 5; c4++) {
                        float4 v = ldc_f4(ra + c4 * 16);
                        acc[pass][c4 * 4 + 0] += v.x * ww;
                        acc[pass][c4 * 4 + 1] += v.y * ww;
                        acc[pass][c4 * 4 + 2] += v.z * ww;
                        acc[pass][c4 * 4 + 3] += v.w * ww;
                    }
                }
            }
            float inv = 1.f / den;
#pragma unroll
            for (int c = 0; c < CC; c++) acc[pass][c] *= inv;
        }
        CLUSTER_SYNC();   // all hG/als reads (local + remote) complete
#pragma unroll
        for (int pass = 0; pass < 2; pass++) {
            int u = t + pass * T;
            if (u >= KK * HH || !act[pass]) continue;
            int j = u / 3, h = u - 3 * j;
#pragma unroll
            for (int c = 0; c < CC; c++) s_hG[j * 64 + h * CC + c] = acc[pass][c];
        }
    }
    __syncthreads();

    // ---- readout: sum OWNED pooled rows -> partial 60-vector ----
    {
        int col = t & 63, grp = t >> 6;       // 16 groups of 64
        if (col < 60) {
            float a = 0.f;
            for (int r = grp; r < KK; r += 16)
                if ((s_perm[r] >> 10) == (int)rank) a += s_hG[r * 64 + col];
            s_part[grp * 60 + col] = a;
        }
    }
    __syncthreads();
    if (t < 60) {
        float a = 0.f;
#pragma unroll
        for (int q = 0; q < 16; q++) a += s_part[q * 60 + t];
        s_gsum[t] = a;
    }
    CLUSTER_SYNC();     // both partials ready

    // ---- rank 0: combine + MLP + log_softmax + write out ----
    if (rank == 0) {
        if (t < 60)
            s_gsum[t] += ldc_f32(mapa_u32(s2u(&s_gsum[t]), 1u)) + (float)KK * bg[t];
        __syncthreads();
        if (t < 30) {
            float v = bf1[t];
#pragma unroll
            for (int c = 0; c < 60; c++) v += s_gsum[c] * Wf1[c * 30 + t];
            s_hb[t] = v > 0.f ? v : 0.f;
        }
        __syncthreads();
        if (t < 3) {
            float v = bf2[t];
#pragma unroll
            for (int c = 0; c < 30; c++) v += s_hb[c] * Wf2[c * 3 + t];
            s_zb[t] = v;
        }
        __syncthreads();
        if (t == 0) {
            float m = fmaxf(s_zb[0], fmaxf(s_zb[1], s_zb[2]));
            float lse = logf(expf(s_zb[0] - m) + expf(s_zb[1] - m) + expf(s_zb[2] - m)) + m;
            out[g * 3 + 0] = s_zb[0] - lse;
            out[g * 3 + 1] = s_zb[1] - lse;
            out[g * 3 + 2] = s_zb[2] - lse;
        }
    }
    CLUSTER_SYNC();     // keep peer smem alive until rank 0 is done
}

// ---------------- launch -----------------------------------------------------
extern "C" void kernel_launch(void* const* d_in, const int* in_sizes, int n_in,
                              void* d_out, int out_size) {
    const float* x     = (const float*)d_in[0];
    const int*   src   = (const int*)d_in[1];
    const int*   dst   = (const int*)d_in[2];
    const float* W1    = (const float*)d_in[4];
    const float* b1    = (const float*)d_in[5];
    const float* Ws    = (const float*)d_in[6];
    const float* bs    = (const float*)d_in[7];
    const float* Wg    = (const float*)d_in[8];
    const float* a_src = (const float*)d_in[9];
    const float* a_dst = (const float*)d_in[10];
    const float* bg    = (const float*)d_in[11];
    const float* Wf1   = (const float*)d_in[12];
    const float* bf1   = (const float*)d_in[13];
    const float* Wf2   = (const float*)d_in[14];
    const float* bf2   = (const float*)d_in[15];
    float* out = (float*)d_out;

    static int attr_set = 0;
    if (!attr_set) {
        cudaFuncSetAttribute(k_mega, cudaFuncAttributeMaxDynamicSharedMemorySize,
                             SMEM_TOTAL);
        attr_set = 1;
    }
    k_mega<<<NGR * 2, T, SMEM_TOTAL>>>(x, src, dst, W1, b1, Ws, bs, Wg,
                                       a_src, a_dst, bg, Wf1, bf1, Wf2, bf2, out);
}

// round 16
// speedup vs baseline: 1.0548x; 1.0548x over previous
#include <cuda_runtime.h>
#include <cstdint>

#define NGR  64
#define NN   2048
#define NH   1024            // nodes per half (per CTA)
#define EPG  16384           // edges per graph
#define KK   410
#define HH   3
#define CC   20
#define T    1024
#define NW   (T / 32)        // 32 — scan_ex relies on NW == 32
#define EPT  (EPG / T)       // 16 edges cached per thread
#define CAP  25              // bucket slots per node (P(Pois(8)>=26)~6e-8)

// ---------------- dynamic smem layout (bytes, per CTA) ----------------------
// Region A (104960 B): bucket CSR int[1024*25]=102400 during build ->
//   hh1/x1 rows of 12 floats -> hG rows of 64 floats by pooled j.
#define SZ_A     104960
#define O_CSR    SZ_A                   // int[10240] packed own-half CSR
#define O_CNT    (O_CSR + 40960)        // int[1024]
#define O_OFF    (O_CNT + 4096)         // int[1024]
#define O_CUR    (O_OFF + 4096)         // int[1024] overflow cursors
#define O_DINV   (O_CUR + 4096)         // float[2048]
#define O_HSS    (O_DINV + 8192)        // hss; radix bins; als+perm later
#define O_SCR    (O_HSS + 8192)         // score own half; ald later
#define O_ENC    (O_SCR + 8192)         // u32[2048]
#define O_NEW    (O_ENC + 8192)         // member list (select); newidx; temps
#define SMEM_TOTAL (O_NEW + 8192)       // 199168

#define O_ALS    O_HSS                  // float[1230]
#define O_PERM   (O_HSS + 4920)         // int[410]
#define O_PART   O_NEW                  // float[16*60]
#define O_GSUM   (O_NEW + 3840)         // float[60]
#define O_HB     (O_NEW + 4352)         // float[30]
#define O_ZB     (O_NEW + 4480)         // float[3]

__device__ __forceinline__ float lrelu(float x) { return x > 0.f ? x : 0.2f * x; }
__device__ __forceinline__ unsigned encf(float f) {
    unsigned u = __float_as_uint(f);
    return (u & 0x80000000u) ? ~u : (u | 0x80000000u);
}
__device__ __forceinline__ uint32_t s2u(const void* p) {
    return (uint32_t)__cvta_generic_to_shared(p);
}
__device__ __forceinline__ uint32_t mapa_u32(uint32_t a, uint32_t r) {
    uint32_t d; asm("mapa.shared::cluster.u32 %0, %1, %2;" : "=r"(d) : "r"(a), "r"(r));
    return d;
}
__device__ __forceinline__ float ldc_f32(uint32_t a) {
    float v; asm volatile("ld.shared::cluster.f32 %0, [%1];" : "=f"(v) : "r"(a)); return v;
}
__device__ __forceinline__ unsigned ldc_u32(uint32_t a) {
    unsigned v; asm volatile("ld.shared::cluster.u32 %0, [%1];" : "=r"(v) : "r"(a)); return v;
}
__device__ __forceinline__ float4 ldc_f4(uint32_t a) {
    float4 v;
    asm volatile("ld.shared::cluster.v4.f32 {%0,%1,%2,%3}, [%4];"
                 : "=f"(v.x), "=f"(v.y), "=f"(v.z), "=f"(v.w) : "r"(a));
    return v;
}
#define CLUSTER_SYNC() do { \
    asm volatile("barrier.cluster.arrive.aligned;" ::: "memory"); \
    asm volatile("barrier.cluster.wait.aligned;" ::: "memory"); } while (0)

// block-wide exclusive scan; 2 barriers. Requires NW == 32.
// NOTE: the leading barrier orders PRIOR smem traffic, but the caller's
// input `s` must already be race-free (read after an explicit barrier).
__device__ __forceinline__ int scan_ex(int s, int t, int* wsum) {
    __syncthreads();
    int lane = t & 31, wid = t >> 5;
    int x = s;
#pragma unroll
    for (int d = 1; d < 32; d <<= 1) {
        int y = __shfl_up_sync(0xFFFFFFFFu, x, d);
        if (lane >= d) x += y;
    }
    if (lane == 31) wsum[wid] = x;
    __syncthreads();
    int w = wsum[lane];
    int incl = w;
#pragma unroll
    for (int d = 1; d < 32; d <<= 1) {
        int y = __shfl_up_sync(0xFFFFFFFFu, incl, d);
        if (lane >= d) incl += y;
    }
    int wpre = __shfl_sync(0xFFFFFFFFu, incl - w, wid);
    return wpre + x - s;
}

__global__ void __launch_bounds__(T, 1) __cluster_dims__(2, 1, 1)
k_mega(const float* __restrict__ x,
       const int* __restrict__ src, const int* __restrict__ dst,
       const float* __restrict__ W1, const float* __restrict__ b1,
       const float* __restrict__ Ws, const float* __restrict__ bs,
       const float* __restrict__ Wg,
       const float* __restrict__ a_src, const float* __restrict__ a_dst,
       const float* __restrict__ bg,
       const float* __restrict__ Wf1, const float* __restrict__ bf1,
       const float* __restrict__ Wf2, const float* __restrict__ bf2,
       float* __restrict__ out)
{
    extern __shared__ char sm[];
    int*      s_bkt  = (int*)(sm);                   // bucket CSR (build only)
    float*    s_hx   = (float*)(sm);                 // rows of 12 (after build)
    float*    s_hG   = (float*)(sm);                 // rows of 64 by global j
    int*      s_csr  = (int*)(sm + O_CSR);
    int*      s_cnt  = (int*)(sm + O_CNT);
    int*      s_off  = (int*)(sm + O_OFF);
    int*      s_cur  = (int*)(sm + O_CUR);
    float*    s_dinv = (float*)(sm + O_DINV);
    float*    s_hss  = (float*)(sm + O_HSS);
    int*      s_bins = (int*)(sm + O_HSS);
    float*    s_als  = (float*)(sm + O_ALS);
    int*      s_perm = (int*)(sm + O_PERM);
    float*    s_scr  = (float*)(sm + O_SCR);
    float*    s_ald  = (float*)(sm + O_SCR);
    unsigned* s_enc  = (unsigned*)(sm + O_ENC);
    int*      s_new  = (int*)(sm + O_NEW);
    int*      s_mem  = (int*)(sm + O_NEW);
    float*    s_part = (float*)(sm + O_PART);
    float*    s_gsum = (float*)(sm + O_GSUM);
    float*    s_hb   = (float*)(sm + O_HB);
    float*    s_zb   = (float*)(sm + O_ZB);

    __shared__ float W1s[50], Wss[10], b1s[10], Wgs[600], asr[60], ads[60];
    __shared__ int wsum[NW];
    __shared__ unsigned sPrefix;
    __shared__ int sNeed, sM;
    __shared__ unsigned long long sKT;
    __shared__ int sOvf;
    __shared__ unsigned s_ovf[64];

    const int g    = blockIdx.x >> 1;
    const unsigned rank = blockIdx.x & 1;
    const unsigned peer = rank ^ 1;
    const int t = threadIdx.x;
    const int ebase = g * EPG;
    const int nbase = g * NN;
    const int hbase = (int)rank * NH;
    const float bs0 = bs[0];

    // ---- P0: register-cache full edge list + init + weights ----
    unsigned er[EPT];
    {
        const int4* s4 = (const int4*)(src + ebase);
        const int4* d4 = (const int4*)(dst + ebase);
#pragma unroll
        for (int r = 0; r < EPT / 4; r++) {
            int4 dv = d4[t + r * T];
            int4 sv = s4[t + r * T];
            er[r * 4 + 0] = ((unsigned)(dv.x & (NN - 1)) << 11) | (unsigned)(sv.x & (NN - 1));
            er[r * 4 + 1] = ((unsigned)(dv.y & (NN - 1)) << 11) | (unsigned)(sv.y & (NN - 1));
            er[r * 4 + 2] = ((unsigned)(dv.z & (NN - 1)) << 11) | (unsigned)(sv.z & (NN - 1));
            er[r * 4 + 3] = ((unsigned)(dv.w & (NN - 1)) << 11) | (unsigned)(sv.w & (NN - 1));
        }
    }
    s_cnt[t] = 0;
    if (t == 0) sOvf = 0;
    if (t < 50) W1s[t] = W1[t];
    if (t < 10) { Wss[t] = Ws[t]; b1s[t] = b1[t]; }
    if (t < 600) Wgs[t] = Wg[t];
    if (t < 60) { asr[t] = a_src[t]; ads[t] = a_dst[t]; }
    __syncthreads();

    // ---- P1': bucket fill — ONE atomic per edge (own-half dsts only) ----
#pragma unroll
    for (int r = 0; r < EPT; r++) {
        if ((er[r] >> 21) == rank) {
            int dl = (int)((er[r] >> 11) & (NH - 1));
            int pos = atomicAdd(&s_cnt[dl], 1);
            if (pos < CAP) s_bkt[dl * CAP + pos] = (int)(er[r] & (NN - 1));
            else { int o = atomicAdd(&sOvf, 1); if (o < 64) s_ovf[o] = er[r]; }
        }
    }
    __syncthreads();    // FIX (r15 bug): counts must be final BEFORE reading

    // ---- P2a: scan + own dinv ----
    int myoff, myn;
    {
        int v = s_cnt[t];
        int ex = scan_ex(v, t, wsum);
        s_off[t] = ex;
        myoff = ex;
        myn = min(v, CAP);
        s_cur[t] = ex + myn;               // overflow insert cursor
        s_dinv[hbase + t] = rsqrtf((float)v + 1.0f);
    }

    // ---- P3': atomic-free compaction bucket -> packed CSR (own range) ----
    for (int e = 0; e < myn; e++)
        s_csr[myoff + e] = s_bkt[t * CAP + e];
    __syncthreads();                        // cur/csr ready; sOvf visible
    if (t < sOvf) {                         // nearly always zero
        unsigned w = s_ovf[t];
        int dl = (int)((w >> 11) & (NH - 1));
        s_csr[atomicAdd(&s_cur[dl], 1)] = (int)(w & (NN - 1));
    }

    // ---- prefetch x into regs; LDG flies during cluster wait ----
    float xi0[5], xi1[5];
    {
        const float* xb = x + (size_t)nbase * 5;
#pragma unroll
        for (int c = 0; c < 5; c++) xi0[c] = xb[t * 5 + c];
#pragma unroll
        for (int c = 0; c < 5; c++) xi1[c] = xb[(t + T) * 5 + c];
    }
    CLUSTER_SYNC();     // own dinv half + CSR done in both CTAs

    // ---- P2b: copy peer dinv half; P4: hh1 for ALL nodes (replicated) ----
    {
        int i = (int)peer * NH + t;
        s_dinv[i] = ldc_f32(mapa_u32(s2u(&s_dinv[i]), peer));
    }
    __syncthreads();    // also: bucket reads done before hh1 overwrites region A
#pragma unroll
    for (int q = 0; q < 2; q++) {
        int i = t + q * T;
        float dv = s_dinv[i];
        const float* xi = q ? xi1 : xi0;
        float h[12];
#pragma unroll
        for (int k = 0; k < 10; k++) {
            float vv = 0.f;
#pragma unroll
            for (int c = 0; c < 5; c++) vv += xi[c] * W1s[c * 10 + k];
            h[k] = vv * dv;
        }
        h[10] = 0.f; h[11] = 0.f;
        float4* o = (float4*)&s_hx[i * 12];
        o[0] = make_float4(h[0], h[1], h[2], h[3]);
        o[1] = make_float4(h[4], h[5], h[6], h[7]);
        o[2] = make_float4(h[8], h[9], h[10], h[11]);
    }
    __syncthreads();

    // ---- P5: GCN1 gather for own 1024 dsts + scorer hss ----
    {
        int i = hbase + t;
        const float4* me = (const float4*)&s_hx[i * 12];
        float4 a0 = me[0], a1 = me[1], a2 = me[2];
        int e0 = s_off[t], e1 = s_off[t] + s_cnt[t];
        for (int e = e0; e < e1; e++) {
            const float4* r = (const float4*)&s_hx[s_csr[e] * 12];
            float4 r0 = r[0], r1 = r[1], r2 = r[2];
            a0.x += r0.x; a0.y += r0.y; a0.z += r0.z; a0.w += r0.w;
            a1.x += r1.x; a1.y += r1.y; a1.z += r1.z; a1.w += r1.w;
            a2.x += r2.x; a2.y += r2.y;
        }
        __syncthreads();     // all local hh1 reads done before x1 overwrite
        float dv = s_dinv[i];
        float v[10] = {a0.x, a0.y, a0.z, a0.w, a1.x, a1.y, a1.z, a1.w, a2.x, a2.y};
        float hs = 0.f;
#pragma unroll
        for (int k = 0; k < 10; k++) {
            v[k] = v[k] * dv + b1s[k];
            hs += v[k] * Wss[k];
        }
        float4* o = (float4*)&s_hx[i * 12];
        o[0] = make_float4(v[0], v[1], v[2], v[3]);
        o[1] = make_float4(v[4], v[5], v[6], v[7]);
        o[2] = make_float4(v[8], v[9], 0.f, 0.f);
        s_hss[i] = hs * dv;
    }
    CLUSTER_SYNC();     // peer hss half ready

    // ---- P5b: copy peer hss half ----
    {
        int i = (int)peer * NH + t;
        s_hss[i] = ldc_f32(mapa_u32(s2u(&s_hss[i]), peer));
    }
    __syncthreads();

    // ---- P6: scorer gather for own dsts -> score + enc ----
    {
        int i = hbase + t;
        float sc = s_hss[i];
        int e0 = s_off[t], e1 = e0 + s_cnt[t];
        for (int e = e0; e < e1; e++) sc += s_hss[s_csr[e]];
        sc = sc * s_dinv[i] + bs0;
        s_scr[i] = sc;
        s_enc[i] = encf(sc);
    }
    CLUSTER_SYNC();     // peer enc half ready

    // ---- P6b: copy peer enc half ----
    {
        int i = (int)peer * NH + t;
        s_enc[i] = ldc_u32(mapa_u32(s2u(&s_enc[i]), peer));
    }
    __syncthreads();
    unsigned e0v = s_enc[2 * t];
    unsigned e1v = s_enc[2 * t + 1];

    // ---- P7: top-K — 2 radix passes (11+11 bits) + exact member stage ----
    {
        int i0 = 2 * t;
        if (t == 0) sM = 0;

        s_bins[i0] = 0; s_bins[i0 + 1] = 0;
        __syncthreads();
        atomicAdd(&s_bins[e0v >> 21], 1);
        atomicAdd(&s_bins[e1v >> 21], 1);
        __syncthreads();
        int c0 = s_bins[2047 - i0], c1 = s_bins[2046 - i0];
        int ex = scan_ex(c0 + c1, t, wsum);
        if (ex < KK && KK <= ex + c0)                 { sPrefix = (unsigned)(2047 - i0); sNeed = KK - ex; }
        else if (ex + c0 < KK && KK <= ex + c0 + c1)  { sPrefix = (unsigned)(2046 - i0); sNeed = KK - ex - c0; }
        __syncthreads();
        unsigned pfx0 = sPrefix;
        int need0 = sNeed;

        s_bins[i0] = 0; s_bins[i0 + 1] = 0;
        __syncthreads();
        if ((e0v >> 21) == pfx0) atomicAdd(&s_bins[(e0v >> 10) & 2047], 1);
        if ((e1v >> 21) == pfx0) atomicAdd(&s_bins[(e1v >> 10) & 2047], 1);
        __syncthreads();
        c0 = s_bins[2047 - i0]; c1 = s_bins[2046 - i0];
        ex = scan_ex(c0 + c1, t, wsum);
        if (ex < need0 && need0 <= ex + c0)                 { sPrefix = (pfx0 << 11) | (unsigned)(2047 - i0); sNeed = need0 - ex; }
        else if (ex + c0 < need0 && need0 <= ex + c0 + c1)  { sPrefix = (pfx0 << 11) | (unsigned)(2046 - i0); sNeed = need0 - ex - c0; }
        __syncthreads();
        unsigned pfx22 = sPrefix;
        int need1 = sNeed;

        if ((e0v >> 10) == pfx22) s_mem[atomicAdd(&sM, 1)] = i0;
        if ((e1v >> 10) == pfx22) s_mem[atomicAdd(&sM, 1)] = i0 + 1;
        __syncthreads();
        int M = sM;
        for (int m = t; m < M; m += T) {
            int im = s_mem[m];
            unsigned long long km =
                ((unsigned long long)s_enc[im] << 11) | (unsigned)(2047 - im);
            int r = 0;
            for (int q = 0; q < M; q++) {
                int iq = s_mem[q];
                unsigned long long kq =
                    ((unsigned long long)s_enc[iq] << 11) | (unsigned)(2047 - iq);
                r += (kq > km) ? 1 : 0;
            }
            if (r == need1 - 1) sKT = km;
        }
        __syncthreads();
        unsigned long long KT = sKT;

        unsigned long long k0 = ((unsigned long long)e0v << 11) | (unsigned)(2047 - i0);
        unsigned long long k1 = ((unsigned long long)e1v << 11) | (unsigned)(2046 - i0);
        int p0 = (k0 >= KT) ? 1 : 0;
        int p1 = (k1 >= KT) ? 1 : 0;
        int exg = scan_ex(p0 + p1, t, wsum);
        if (p0) { s_perm[exg] = i0; s_new[i0] = exg; } else s_new[i0] = -1;
        if (p1) { s_perm[exg + p0] = i0 + 1; s_new[i0 + 1] = exg + p0; }
        else s_new[i0 + 1] = -1;
    }
    __syncthreads();

    // ---- P8: pooled precompute for OWNED (node,head) units (gate inline) ----
    {
        float hg[2][CC], as2[2], ad2[2];
        bool act[2] = {false, false};
#pragma unroll
        for (int pass = 0; pass < 2; pass++) {
            int u = t + pass * T;
            if (u >= KK * HH) break;
            int j = u / 3, h = u - 3 * j;
            int node = s_perm[j];
            if ((node >> 10) != (int)rank) continue;
            act[pass] = true;
            float gate = tanhf(s_scr[node]);
            float xp[10];
#pragma unroll
            for (int c = 0; c < 10; c++) xp[c] = s_hx[node * 12 + c] * gate;
            float as = 0.f, ad = 0.f;
#pragma unroll
            for (int c = 0; c < CC; c++) {
                int k = h * CC + c;
                float v = 0.f;
#pragma unroll
                for (int q = 0; q < 10; q++) v += xp[q] * Wgs[q * 60 + k];
                hg[pass][c] = v;
                as += v * asr[k];
                ad += v * ads[k];
            }
            as2[pass] = as; ad2[pass] = ad;
        }
        __syncthreads();
#pragma unroll
        for (int pass = 0; pass < 2; pass++) {
            int u = t + pass * T;
            if (u >= KK * HH || !act[pass]) continue;
            int j = u / 3, h = u - 3 * j;
#pragma unroll
            for (int c = 0; c < CC; c++) s_hG[j * 64 + h * CC + c] = hg[pass][c];
            s_als[u] = as2[pass];
            s_ald[u] = ad2[pass];
        }
    }
    CLUSTER_SYNC();     // peer hG rows + als entries final

    // ---- P9: GAT softmax-aggregate for owned units; peer als/hG via DSMEM ----
    {
        float acc[2][CC];
        bool act[2] = {false, false};
#pragma unroll
        for (int pass = 0; pass < 2; pass++) {
            int u = t + pass * T;
            if (u >= KK * HH) break;
            int j = u / 3, h = u - 3 * j;
            int node = s_perm[j];
            if ((node >> 10) != (int)rank) continue;
            act[pass] = true;
            float aldj = s_ald[u];
            float w = __expf(lrelu(s_als[u] + aldj));
            float den = w;
#pragma unroll
            for (int c = 0; c < CC; c++) acc[pass][c] = s_hG[j * 64 + h * CC + c] * w;
            int nl = node & (NH - 1);
            int e0 = s_off[nl], e1 = e0 + s_cnt[nl];
            for (int e = e0; e < e1; e++) {
                int sj = s_new[s_csr[e]];
                if (sj < 0) continue;
                bool rem = ((s_perm[sj] >> 10) != (int)rank);
                float alsj = rem
                    ? ldc_f32(mapa_u32(s2u(&s_als[sj * 3 + h]), peer))
                    : s_als[sj * 3 + h];
                float ww = __expf(lrelu(alsj + aldj));
                den += ww;
                if (!rem) {
                    const float* row = &s_hG[sj * 64 + h * CC];
#pragma unroll
                    for (int c = 0; c < CC; c++) acc[pass][c] += row[c] * ww;
                } else {
                    uint32_t ra = mapa_u32(s2u(&s_hG[sj * 64 + h * CC]), peer);
#pragma unroll
                    for (int c4 = 0; c4 < 5; c4++) {
                        float4 v = ldc_f4(ra + c4 * 16);
                        acc[pass][c4 * 4 + 0] += v.x * ww;
                        acc[pass][c4 * 4 + 1] += v.y * ww;
                        acc[pass][c4 * 4 + 2] += v.z * ww;
                        acc[pass][c4 * 4 + 3] += v.w * ww;
                    }
                }
            }
            float inv = 1.f / den;
#pragma unroll
            for (int c = 0; c < CC; c++) acc[pass][c] *= inv;
        }
        CLUSTER_SYNC();
#pragma unroll
        for (int pass = 0; pass < 2; pass++) {
            int u = t + pass * T;
            if (u >= KK * HH || !act[pass]) continue;
            int j = u / 3, h = u - 3 * j;
#pragma unroll
            for (int c = 0; c < CC; c++) s_hG[j * 64 + h * CC + c] = acc[pass][c];
        }
    }
    __syncthreads();

    // ---- readout: sum OWNED pooled rows -> partial 60-vector ----
    {
        int col = t & 63, grp = t >> 6;       // 16 groups of 64
        if (col < 60) {
            float a = 0.f;
            for (int r = grp; r < KK; r += 16)
                if ((s_perm[r] >> 10) == (int)rank) a += s_hG[r * 64 + col];
            s_part[grp * 60 + col] = a;
        }
    }
    __syncthreads();
    if (t < 60) {
        float a = 0.f;
#pragma unroll
        for (int q = 0; q < 16; q++) a += s_part[q * 60 + t];
        s_gsum[t] = a;
    }
    CLUSTER_SYNC();     // both partials ready

    // ---- rank 0: combine + MLP + log_softmax + write out ----
    if (rank == 0) {
        if (t < 60)
            s_gsum[t] += ldc_f32(mapa_u32(s2u(&s_gsum[t]), 1u)) + (float)KK * bg[t];
        __syncthreads();
        if (t < 30) {
            float v = bf1[t];
#pragma unroll
            for (int c = 0; c < 60; c++) v += s_gsum[c] * Wf1[c * 30 + t];
            s_hb[t] = v > 0.f ? v : 0.f;
        }
        __syncthreads();
        if (t < 3) {
            float v = bf2[t];
#pragma unroll
            for (int c = 0; c < 30; c++) v += s_hb[c] * Wf2[c * 3 + t];
            s_zb[t] = v;
        }
        __syncthreads();
        if (t == 0) {
            float m = fmaxf(s_zb[0], fmaxf(s_zb[1], s_zb[2]));
            float lse = logf(expf(s_zb[0] - m) + expf(s_zb[1] - m) + expf(s_zb[2] - m)) + m;
            out[g * 3 + 0] = s_zb[0] - lse;
            out[g * 3 + 1] = s_zb[1] - lse;
            out[g * 3 + 2] = s_zb[2] - lse;
        }
    }
    CLUSTER_SYNC();     // keep peer smem alive until rank 0 is done
}

// ---------------- launch -----------------------------------------------------
extern "C" void kernel_launch(void* const* d_in, const int* in_sizes, int n_in,
                              void* d_out, int out_size) {
    const float* x     = (const float*)d_in[0];
    const int*   src   = (const int*)d_in[1];
    const int*   dst   = (const int*)d_in[2];
    const float* W1    = (const float*)d_in[4];
    const float* b1    = (const float*)d_in[5];
    const float* Ws    = (const float*)d_in[6];
    const float* bs    = (const float*)d_in[7];
    const float* Wg    = (const float*)d_in[8];
    const float* a_src = (const float*)d_in[9];
    const float* a_dst = (const float*)d_in[10];
    const float* bg    = (const float*)d_in[11];
    const float* Wf1   = (const float*)d_in[12];
    const float* bf1   = (const float*)d_in[13];
    const float* Wf2   = (const float*)d_in[14];
    const float* bf2   = (const float*)d_in[15];
    float* out = (float*)d_out;

    static int attr_set = 0;
    if (!attr_set) {
        cudaFuncSetAttribute(k_mega, cudaFuncAttributeMaxDynamicSharedMemorySize,
                             SMEM_TOTAL);
        attr_set = 1;
    }
    k_mega<<<NGR * 2, T, SMEM_TOTAL>>>(x, src, dst, W1, b1, Ws, bs, Wg,
                                       a_src, a_dst, bg, Wf1, bf1, Wf2, bf2, out);
}